// round 4
// baseline (speedup 1.0000x reference)
#include <cuda_runtime.h>
#include <cstdint>

// BoundaryBCELoss — register-resident, 2-columns-per-lane version.
//
// Linearity identity: with nonneg inputs, the 5 (dilate+clip) iterations equal
// 5 LINEAR 5-point stencil iterations followed by one min(1, .). Pack (h, o)
// into one f32x2 (u64) and do both masks with add.rn.f32x2.
//
// Each lane owns TWO adjacent columns (A at even c0, B at c0+1):
//   colA.left  = shfl_up(colB)    colA.right = colB (local)
//   colB.left  = colA (local)     colB.right = shfl_down(colA)
// -> 2 shfl.64 per row per iteration for 2 columns (half the shuffles).
// Warp tile: 64 cols (52 valid, halo 6 left / 6 right) x 24 out rows (R=34).

#define IMG_H 384
#define IMG_W 384
#define IMG_N 64
#define HALO   5
#define TOUT_H 24
#define R      (TOUT_H + 2*HALO)   // 34 rows per lane
#define VOUT   52                  // valid output cols per warp
#define PX     8                   // ceil(384/52) column panels
#define SY     (IMG_H / TOUT_H)    // 16 row strips
#define WPB    4                   // warps per block
#define NTHREADS 128
#define NTILES  (PX * SY * IMG_N)      // 8192
#define NBLOCKS (NTILES / WPB)         // 2048

typedef unsigned long long u64;

__device__ __forceinline__ u64 f2add(u64 a, u64 b) {
    u64 d;
    asm("add.rn.f32x2 %0, %1, %2;" : "=l"(d) : "l"(a), "l"(b));
    return d;
}

__device__ __forceinline__ u64 f2pack(float lo, float hi) {
    return (u64)__float_as_uint(lo) | ((u64)__float_as_uint(hi) << 32);
}

__global__ void bbl_init_out(float* out) { out[0] = 0.0f; }

__global__ __launch_bounds__(NTHREADS, 3)
void bbl_reg2_kernel(const float* __restrict__ hand,
                     const float* __restrict__ obj,
                     const float* __restrict__ targ,
                     float* __restrict__ out)
{
    __shared__ float wsum[WPB];

    const int tid  = threadIdx.x;
    const int lane = tid & 31;
    const int warp = tid >> 5;

    const int tile = blockIdx.x * WPB + warp;
    const int n    = tile / (PX * SY);
    const int rm   = tile - n * (PX * SY);
    const int sy   = rm / PX;
    const int px   = rm - sy * PX;

    const int c0 = px * VOUT - 6 + 2 * lane;   // even -> float2-aligned
    const int y0 = sy * TOUT_H - HALO;
    const size_t base = (size_t)n * IMG_H * IMG_W;
    const bool cok = ((unsigned)c0 < (unsigned)IMG_W);  // c0 even => c0+1 <= 383 too

    // ---- load R-row double column of both masks, packed (h,o) per column ----
    u64 vA[R], vB[R];
    #pragma unroll
    for (int r = 0; r < R; ++r) {
        const int y = y0 + r;
        float2 h2 = make_float2(0.0f, 0.0f);
        float2 o2 = make_float2(0.0f, 0.0f);
        if (cok && (unsigned)y < (unsigned)IMG_H) {
            const size_t g = base + (size_t)y * IMG_W + c0;
            h2 = *reinterpret_cast<const float2*>(hand + g);
            o2 = *reinterpret_cast<const float2*>(obj  + g);
        }
        vA[r] = f2pack(h2.x, o2.x);
        vB[r] = f2pack(h2.y, o2.y);
    }

    // ---- 5 linear 5-point stencil iterations, all in registers ----
    #pragma unroll 1
    for (int it = 0; it < 5; ++it) {
        u64 aA = 0ULL, aB = 0ULL;          // rows above (init = zero padding)
        #pragma unroll
        for (int r = 0; r < R; ++r) {
            const u64 cA = vA[r];
            const u64 cB = vB[r];
            const u64 bA = (r < R - 1) ? vA[r + 1] : 0ULL;
            const u64 bB = (r < R - 1) ? vB[r + 1] : 0ULL;
            const u64 lA = __shfl_up_sync(0xffffffffu, cB, 1);   // colA left
            const u64 rB = __shfl_down_sync(0xffffffffu, cA, 1); // colB right
            u64 sA = f2add(f2add(aA, bA), f2add(lA, cB));
            sA = f2add(sA, cA);
            u64 sB = f2add(f2add(aB, bB), f2add(cA, rB));
            sB = f2add(sB, cB);
            aA = cA; aB = cB;
            vA[r] = sA; vB[r] = sB;
        }
    }

    // ---- BCE over this warp-tile's valid region ----
    // valid lanes: rel cols [6, 58) -> lanes 3..28 (both columns), plus c0<384
    float acc = 0.0f;
    if (lane >= 3 && lane <= 28 && cok) {
        #pragma unroll
        for (int r = HALO; r < HALO + TOUT_H; ++r) {
            const int y = y0 + r;                      // in [0, 384)
            const float2 t2 = *reinterpret_cast<const float2*>(
                targ + base + (size_t)y * IMG_W + c0);

            const float hA = fminf(__uint_as_float((unsigned)(vA[r] & 0xffffffffu)), 1.0f);
            const float oA = fminf(__uint_as_float((unsigned)(vA[r] >> 32)),        1.0f);
            const float pA = hA * oA;
            const float lpA  = fmaxf(__logf(pA),        -100.0f);
            const float l1pA = fmaxf(__logf(1.0f - pA), -100.0f);
            acc += l1pA + t2.x * (lpA - l1pA);

            const float hB = fminf(__uint_as_float((unsigned)(vB[r] & 0xffffffffu)), 1.0f);
            const float oB = fminf(__uint_as_float((unsigned)(vB[r] >> 32)),        1.0f);
            const float pB = hB * oB;
            const float lpB  = fmaxf(__logf(pB),        -100.0f);
            const float l1pB = fmaxf(__logf(1.0f - pB), -100.0f);
            acc += l1pB + t2.y * (lpB - l1pB);
        }
    }

    // ---- warp then block reduction, one atomic per block ----
    #pragma unroll
    for (int off = 16; off > 0; off >>= 1)
        acc += __shfl_down_sync(0xffffffffu, acc, off);
    if (lane == 0) wsum[warp] = acc;
    __syncthreads();
    if (tid == 0) {
        float s = 0.0f;
        #pragma unroll
        for (int w = 0; w < WPB; ++w) s += wsum[w];
        const float scale = -1.0f / ((float)IMG_N * IMG_H * IMG_W);
        atomicAdd(out, s * scale);
    }
}

extern "C" void kernel_launch(void* const* d_in, const int* in_sizes, int n_in,
                              void* d_out, int out_size)
{
    const float* hand = (const float*)d_in[0];
    const float* obj  = (const float*)d_in[1];
    const float* targ = (const float*)d_in[2];
    float* out = (float*)d_out;

    bbl_init_out<<<1, 1>>>(out);
    bbl_reg2_kernel<<<NBLOCKS, NTHREADS>>>(hand, obj, targ, out);
}

// round 6
// speedup vs baseline: 1.3086x; 1.3086x over previous
#include <cuda_runtime.h>
#include <cstdint>

// BoundaryBCELoss — streaming line-buffer pipeline, 2 columns per lane.
//
// Linearity identity: with nonneg inputs, 5x (dilate + clip[0,1]) equals
// 5 LINEAR 5-point stencil iterations followed by one min(1, .). Pack
// (hand, obj) into one f32x2 (u64): both masks per add.rn.f32x2.
//
// Streaming: rows flow top->bottom through a 5-stage pipeline; stage k keeps
// only a 2-row window (prev, cur). Input row yi produces stage-5 row yi-5,
// which is immediately consumed by the BCE accumulator. Live registers stay
// ~constant regardless of strip height (fixes R3's spill regression).
//
// Each lane owns two adjacent columns (A at even c0, B at c0+1):
//   colA.left = shfl_up(colB), colA.right = colB (local)
//   colB.left = colA (local),  colB.right = shfl_down(colA)
// Warp tile: 64 cols (52 valid, 6-col halo each side) x 48 output rows
// (58 input rows incl. 5-row warmup/tail halo).

#define IMG_H 384
#define IMG_W 384
#define IMG_N 64
#define WARM   5
#define TH     48                  // output rows per strip
#define RITER  (TH + 2*WARM)       // 58 input rows streamed
#define VOUT   52                  // valid output cols per warp
#define PX     8                   // ceil(384/52) column panels
#define SY     (IMG_H / TH)        // 8 row strips
#define WPB    4
#define NTHREADS 128
#define NTILES  (PX * SY * IMG_N)      // 4096 warp-tiles
#define NBLOCKS (NTILES / WPB)         // 1024

typedef unsigned long long u64;

__device__ __forceinline__ u64 f2add(u64 a, u64 b) {
    u64 d;
    asm("add.rn.f32x2 %0, %1, %2;" : "=l"(d) : "l"(a), "l"(b));
    return d;
}

__device__ __forceinline__ u64 f2pack(float lo, float hi) {
    return (u64)__float_as_uint(lo) | ((u64)__float_as_uint(hi) << 32);
}

__global__ void bbl_init_out(float* out) { out[0] = 0.0f; }

__global__ __launch_bounds__(NTHREADS, 5)
void bbl_stream_kernel(const float* __restrict__ hand,
                       const float* __restrict__ obj,
                       const float* __restrict__ targ,
                       float* __restrict__ out)
{
    __shared__ float wsum[WPB];

    const int tid  = threadIdx.x;
    const int lane = tid & 31;
    const int warp = tid >> 5;

    const int tile = blockIdx.x * WPB + warp;
    const int n    = tile / (PX * SY);
    const int rm   = tile - n * (PX * SY);
    const int sy   = rm / PX;
    const int px   = rm - sy * PX;

    const int c0 = px * VOUT - 6 + 2 * lane;    // even -> float2-aligned
    const int Y0 = sy * TH;
    const size_t base = (size_t)n * IMG_H * IMG_W;
    const bool cok = ((unsigned)c0 < (unsigned)IMG_W);

    // running row pointers (deref only when row predicate passes)
    const float* hp = hand + base + (size_t)(Y0 - WARM) * IMG_W + c0;
    const float* op = obj  + base + (size_t)(Y0 - WARM) * IMG_W + c0;
    const float* tp = targ + base + (size_t)(Y0 - WARM) * IMG_W + c0;

    // 5-stage pipeline windows (prev, cur) per stage per column, zero-init
    u64 pA[5], cA[5], pB[5], cB[5];
    #pragma unroll
    for (int k = 0; k < 5; ++k) { pA[k] = cA[k] = pB[k] = cB[k] = 0ULL; }

    float acc = 0.0f;
    int yi = Y0 - WARM;

    #pragma unroll 2
    for (int i = 0; i < RITER; ++i) {
        // ---- load input row yi (zero outside image) ----
        float2 h2 = make_float2(0.0f, 0.0f);
        float2 o2 = make_float2(0.0f, 0.0f);
        if (cok && (unsigned)yi < (unsigned)IMG_H) {
            h2 = *reinterpret_cast<const float2*>(hp);
            o2 = *reinterpret_cast<const float2*>(op);
        }
        u64 nA = f2pack(h2.x, o2.x);
        u64 nB = f2pack(h2.y, o2.y);

        // ---- 5-stage cascade: stage k emits row yi-(k+1) of iteration k+1 ----
        #pragma unroll
        for (int k = 0; k < 5; ++k) {
            const u64 lA = __shfl_up_sync(0xffffffffu, cB[k], 1);   // colA left
            const u64 rB = __shfl_down_sync(0xffffffffu, cA[k], 1); // colB right
            u64 oA = f2add(f2add(pA[k], nA), f2add(lA, cB[k]));
            oA = f2add(oA, cA[k]);
            u64 oB = f2add(f2add(pB[k], nB), f2add(cA[k], rB));
            oB = f2add(oB, cB[k]);
            pA[k] = cA[k]; cA[k] = nA;
            pB[k] = cB[k]; cB[k] = nB;
            nA = oA; nB = oB;
        }

        // ---- BCE on stage-5 row y5 = yi - 5 ----
        const int y5 = yi - WARM;
        if ((unsigned)(y5 - Y0) < (unsigned)TH && lane >= 3 && lane <= 28 && cok) {
            const float2 t2 = *reinterpret_cast<const float2*>(tp - (size_t)WARM * IMG_W);

            const float hA = fminf(__uint_as_float((unsigned)(nA & 0xffffffffu)), 1.0f);
            const float oAv = fminf(__uint_as_float((unsigned)(nA >> 32)),        1.0f);
            const float pAv = hA * oAv;
            const float lpA  = fmaxf(__logf(pAv),        -100.0f);
            const float l1pA = fmaxf(__logf(1.0f - pAv), -100.0f);
            acc += l1pA + t2.x * (lpA - l1pA);

            const float hB = fminf(__uint_as_float((unsigned)(nB & 0xffffffffu)), 1.0f);
            const float oBv = fminf(__uint_as_float((unsigned)(nB >> 32)),        1.0f);
            const float pBv = hB * oBv;
            const float lpB  = fmaxf(__logf(pBv),        -100.0f);
            const float l1pB = fmaxf(__logf(1.0f - pBv), -100.0f);
            acc += l1pB + t2.y * (lpB - l1pB);
        }

        hp += IMG_W; op += IMG_W; tp += IMG_W;
        ++yi;
    }

    // ---- warp then block reduction, one atomic per block ----
    #pragma unroll
    for (int off = 16; off > 0; off >>= 1)
        acc += __shfl_down_sync(0xffffffffu, acc, off);
    if (lane == 0) wsum[warp] = acc;
    __syncthreads();
    if (tid == 0) {
        float s = 0.0f;
        #pragma unroll
        for (int w = 0; w < WPB; ++w) s += wsum[w];
        const float scale = -1.0f / ((float)IMG_N * IMG_H * IMG_W);
        atomicAdd(out, s * scale);
    }
}

extern "C" void kernel_launch(void* const* d_in, const int* in_sizes, int n_in,
                              void* d_out, int out_size)
{
    const float* hand = (const float*)d_in[0];
    const float* obj  = (const float*)d_in[1];
    const float* targ = (const float*)d_in[2];
    float* out = (float*)d_out;

    bbl_init_out<<<1, 1>>>(out);
    bbl_stream_kernel<<<NBLOCKS, NTHREADS>>>(hand, obj, targ, out);
}

// round 7
// speedup vs baseline: 1.5468x; 1.1820x over previous
#include <cuda_runtime.h>
#include <cstdint>

// BoundaryBCELoss — streaming 5-stage cascade, 4 columns per lane.
//
// Linearity: with nonneg inputs, 5x (dilate + clip[0,1]) == 5 LINEAR 5-point
// stencil iterations + one final min(1,.). (h,o) packed into one f32x2 (u64);
// both masks advance with a single add.rn.f32x2.
//
// Streaming: rows flow top->bottom through 5 pipeline stages; stage k keeps a
// 2-row window. Lane owns 4 adjacent columns A..D; the only cross-lane data
// per stage is shfl_up(colD) and shfl_down(colA) -> 2 shfl.64 per stage for
// 4 columns. Warp tile: 128 cols (112 valid, 8-col halo) x 32 output rows
// (42 input rows incl. pipeline warmup).

#define IMG_H 384
#define IMG_W 384
#define IMG_N 64
#define WARM   5
#define TH     32
#define RITER  (TH + 2*WARM)       // 42
#define VOUT   112                 // valid output cols per warp
#define PX     4                   // 4*112 = 448 >= 384
#define SY     (IMG_H / TH)        // 12
#define WPB    4
#define NTHREADS 128
#define NTILES  (PX * SY * IMG_N)      // 3072 warp-tiles
#define NBLOCKS (NTILES / WPB)         // 768

typedef unsigned long long u64;

__device__ __forceinline__ u64 f2add(u64 a, u64 b) {
    u64 d;
    asm("add.rn.f32x2 %0, %1, %2;" : "=l"(d) : "l"(a), "l"(b));
    return d;
}
__device__ __forceinline__ u64 f2pack(float lo, float hi) {
    u64 d;
    asm("mov.b64 %0, {%1, %2};" : "=l"(d) : "f"(lo), "f"(hi));
    return d;
}
__device__ __forceinline__ void f2unpack(u64 v, float& lo, float& hi) {
    asm("mov.b64 {%0, %1}, %2;" : "=f"(lo), "=f"(hi) : "l"(v));
}

__global__ void bbl_init_out(float* out) { out[0] = 0.0f; }

__global__ __launch_bounds__(NTHREADS, 4)
void bbl_s4_kernel(const float* __restrict__ hand,
                   const float* __restrict__ obj,
                   const float* __restrict__ targ,
                   float* __restrict__ out)
{
    __shared__ float wsum[WPB];

    const int tid  = threadIdx.x;
    const int lane = tid & 31;
    const int warp = tid >> 5;

    const int tile = blockIdx.x * WPB + warp;
    const int n    = tile / (PX * SY);
    const int rm   = tile - n * (PX * SY);
    const int sy   = rm / PX;
    const int px   = rm - sy * PX;

    const int c0 = px * VOUT - 8 + 4 * lane;    // multiple of 4 -> float4 ok
    const int Y0 = sy * TH;
    const size_t base = (size_t)n * IMG_H * IMG_W;
    const bool cok = ((unsigned)c0 < (unsigned)IMG_W);

    // valid output columns for this panel (no overlap between panels)
    const int vlo = px * VOUT;
    const int vhi = (vlo + VOUT < IMG_W) ? (vlo + VOUT) : IMG_W;
    const bool v0 = (c0     >= vlo) && (c0     < vhi);
    const bool v1 = (c0 + 1 >= vlo) && (c0 + 1 < vhi);
    const bool v2 = (c0 + 2 >= vlo) && (c0 + 2 < vhi);
    const bool v3 = (c0 + 3 >= vlo) && (c0 + 3 < vhi);
    const bool anyv = v0 | v1 | v2 | v3;

    const float* hp = hand + base + (size_t)(Y0 - WARM)     * IMG_W + c0;
    const float* op = obj  + base + (size_t)(Y0 - WARM)     * IMG_W + c0;
    const float* tp = targ + base + (size_t)(Y0 - 2 * WARM) * IMG_W + c0;

    // 5-stage pipeline: (prev, cur) rows per stage per column, zero-init
    u64 pA[WARM], cA[WARM], pB[WARM], cB[WARM];
    u64 pC[WARM], cC[WARM], pD[WARM], cD[WARM];
    #pragma unroll
    for (int k = 0; k < WARM; ++k) {
        pA[k] = cA[k] = pB[k] = cB[k] = 0ULL;
        pC[k] = cC[k] = pD[k] = cD[k] = 0ULL;
    }

    float acc = 0.0f;
    int yi = Y0 - WARM;

    #pragma unroll 2
    for (int i = 0; i < RITER; ++i) {
        // ---- load input row yi for 4 columns (zero outside image) ----
        float4 h4 = make_float4(0.f, 0.f, 0.f, 0.f);
        float4 o4 = make_float4(0.f, 0.f, 0.f, 0.f);
        if (cok && (unsigned)yi < (unsigned)IMG_H) {
            h4 = *reinterpret_cast<const float4*>(hp);
            o4 = *reinterpret_cast<const float4*>(op);
        }
        u64 nA = f2pack(h4.x, o4.x);
        u64 nB = f2pack(h4.y, o4.y);
        u64 nC = f2pack(h4.z, o4.z);
        u64 nD = f2pack(h4.w, o4.w);

        // ---- 5-stage cascade: stage k emits one row of iteration k+1 ----
        #pragma unroll
        for (int k = 0; k < WARM; ++k) {
            const u64 lA = __shfl_up_sync(0xffffffffu,  cD[k], 1);  // colA left
            const u64 rD = __shfl_down_sync(0xffffffffu, cA[k], 1); // colD right
            // out = up + center + left + right + down ; only the final add
            // depends on the previous stage's output (n*), keeping the
            // cross-stage chain short.
            u64 oA = f2add(f2add(pA[k], cA[k]), f2add(lA,    cB[k]));
            u64 oB = f2add(f2add(pB[k], cB[k]), f2add(cA[k], cC[k]));
            u64 oC = f2add(f2add(pC[k], cC[k]), f2add(cB[k], cD[k]));
            u64 oD = f2add(f2add(pD[k], cD[k]), f2add(cC[k], rD));
            oA = f2add(oA, nA);
            oB = f2add(oB, nB);
            oC = f2add(oC, nC);
            oD = f2add(oD, nD);
            pA[k] = cA[k]; cA[k] = nA;
            pB[k] = cB[k]; cB[k] = nB;
            pC[k] = cC[k]; cC[k] = nC;
            pD[k] = cD[k]; cD[k] = nD;
            nA = oA; nB = oB; nC = oC; nD = oD;
        }

        // ---- BCE on stage-5 output row y5 = yi - 5 (valid once i >= 10) ----
        if (i >= 2 * WARM) {                    // warp-uniform condition
            float4 t4 = make_float4(0.f, 0.f, 0.f, 0.f);
            if (anyv) t4 = *reinterpret_cast<const float4*>(tp);

            float h0, q0, h1, q1, h2, q2, h3, q3;
            f2unpack(nA, h0, q0);
            f2unpack(nB, h1, q1);
            f2unpack(nC, h2, q2);
            f2unpack(nD, h3, q3);
            const float p0 = fminf(h0, 1.f) * fminf(q0, 1.f);
            const float p1 = fminf(h1, 1.f) * fminf(q1, 1.f);
            const float p2 = fminf(h2, 1.f) * fminf(q2, 1.f);
            const float p3 = fminf(h3, 1.f) * fminf(q3, 1.f);

            // fast path: p == 1 -> lp = 0, l1p = -100 exactly (>99% of pixels)
            const bool fast = (!v0 | (p0 == 1.f)) & (!v1 | (p1 == 1.f))
                            & (!v2 | (p2 == 1.f)) & (!v3 | (p3 == 1.f));
            if (__all_sync(0xffffffffu, fast)) {
                float s = 0.f;
                if (v0) s += 1.f - t4.x;
                if (v1) s += 1.f - t4.y;
                if (v2) s += 1.f - t4.z;
                if (v3) s += 1.f - t4.w;
                acc -= 100.f * s;
            } else {
                {
                    const float lp  = fmaxf(__logf(p0),       -100.f);
                    const float l1p = fmaxf(__logf(1.f - p0), -100.f);
                    if (v0) acc += l1p + t4.x * (lp - l1p);
                }
                {
                    const float lp  = fmaxf(__logf(p1),       -100.f);
                    const float l1p = fmaxf(__logf(1.f - p1), -100.f);
                    if (v1) acc += l1p + t4.y * (lp - l1p);
                }
                {
                    const float lp  = fmaxf(__logf(p2),       -100.f);
                    const float l1p = fmaxf(__logf(1.f - p2), -100.f);
                    if (v2) acc += l1p + t4.z * (lp - l1p);
                }
                {
                    const float lp  = fmaxf(__logf(p3),       -100.f);
                    const float l1p = fmaxf(__logf(1.f - p3), -100.f);
                    if (v3) acc += l1p + t4.w * (lp - l1p);
                }
            }
        }

        hp += IMG_W; op += IMG_W; tp += IMG_W;
        ++yi;
    }

    // ---- warp then block reduction, one atomic per block ----
    #pragma unroll
    for (int off = 16; off > 0; off >>= 1)
        acc += __shfl_down_sync(0xffffffffu, acc, off);
    if (lane == 0) wsum[warp] = acc;
    __syncthreads();
    if (tid == 0) {
        float s = 0.0f;
        #pragma unroll
        for (int w = 0; w < WPB; ++w) s += wsum[w];
        const float scale = -1.0f / ((float)IMG_N * IMG_H * IMG_W);
        atomicAdd(out, s * scale);
    }
}

extern "C" void kernel_launch(void* const* d_in, const int* in_sizes, int n_in,
                              void* d_out, int out_size)
{
    const float* hand = (const float*)d_in[0];
    const float* obj  = (const float*)d_in[1];
    const float* targ = (const float*)d_in[2];
    float* out = (float*)d_out;

    bbl_init_out<<<1, 1>>>(out);
    bbl_s4_kernel<<<NBLOCKS, NTHREADS>>>(hand, obj, targ, out);
}

// round 11
// speedup vs baseline: 1.6840x; 1.0887x over previous
#include <cuda_runtime.h>
#include <cstdint>

// BoundaryBCELoss — streaming 5-stage cascade, 4 columns/lane,
// software-pipelined global loads (prefetch distance 2).
//
// Linearity: with nonneg inputs, 5x (dilate + clip[0,1]) == 5 LINEAR 5-point
// stencil iterations + one final min(1,.). (h,o) packed into one f32x2 (u64);
// both masks advance with a single add.rn.f32x2.
//
// Rows stream top->bottom through 5 pipeline stages (2-row window each).
// Lane owns 4 adjacent columns A..D; cross-lane traffic is 2 shfl.64/stage.
// Mask row i+2 and target row for iteration i+2 are loaded at the top of
// iteration i (register double-buffer), hiding LDG latency.

#define IMG_H 384
#define IMG_W 384
#define IMG_N 64
#define WARM   5
#define TH     32
#define RITER  (TH + 2*WARM)       // 42
#define VOUT   112                 // valid output cols per warp
#define PX     4                   // 4*112 = 448 >= 384
#define SY     (IMG_H / TH)        // 12
#define WPB    4
#define NTHREADS 128
#define NTILES  (PX * SY * IMG_N)      // 3072 warp-tiles
#define NBLOCKS (NTILES / WPB)         // 768

typedef unsigned long long u64;

__device__ __forceinline__ u64 f2add(u64 a, u64 b) {
    u64 d;
    asm("add.rn.f32x2 %0, %1, %2;" : "=l"(d) : "l"(a), "l"(b));
    return d;
}
__device__ __forceinline__ u64 f2pack(float lo, float hi) {
    u64 d;
    asm("mov.b64 %0, {%1, %2};" : "=l"(d) : "f"(lo), "f"(hi));
    return d;
}
__device__ __forceinline__ void f2unpack(u64 v, float& lo, float& hi) {
    asm("mov.b64 {%0, %1}, %2;" : "=f"(lo), "=f"(hi) : "l"(v));
}

__global__ void bbl_init_out(float* out) { out[0] = 0.0f; }

__global__ __launch_bounds__(NTHREADS, 3)
void bbl_s4p_kernel(const float* __restrict__ hand,
                    const float* __restrict__ obj,
                    const float* __restrict__ targ,
                    float* __restrict__ out)
{
    __shared__ float wsum[WPB];

    const int tid  = threadIdx.x;
    const int lane = tid & 31;
    const int warp = tid >> 5;

    const int tile = blockIdx.x * WPB + warp;
    const int n    = tile / (PX * SY);
    const int rm   = tile - n * (PX * SY);
    const int sy   = rm / PX;
    const int px   = rm - sy * PX;

    const int c0 = px * VOUT - 8 + 4 * lane;    // multiple of 4 -> float4 ok
    const int Y0 = sy * TH;
    const size_t base = (size_t)n * IMG_H * IMG_W;
    const bool cok = ((unsigned)c0 < (unsigned)IMG_W);

    // valid output columns for this panel
    const int vlo = px * VOUT;
    const int vhi = (vlo + VOUT < IMG_W) ? (vlo + VOUT) : IMG_W;
    const bool v0 = (c0     >= vlo) && (c0     < vhi);
    const bool v1 = (c0 + 1 >= vlo) && (c0 + 1 < vhi);
    const bool v2 = (c0 + 2 >= vlo) && (c0 + 2 < vhi);
    const bool v3 = (c0 + 3 >= vlo) && (c0 + 3 < vhi);
    const bool anyv = v0 | v1 | v2 | v3;

    // prefetch pointers: masks point at row (yi + 2); target at the row
    // consumed at iteration i+2, i.e. Y0 + (i+2) - 2*WARM  (init for i=0)
    const float* hp = hand + base + (size_t)(Y0 - WARM + 2) * IMG_W + c0;
    const float* op = obj  + base + (size_t)(Y0 - WARM + 2) * IMG_W + c0;
    const float* tp = targ + base + (size_t)(Y0 + 2 - 2 * WARM) * IMG_W + c0;

    // ---- prolog: load rows for iterations 0 and 1 ----
    const float4 z4 = make_float4(0.f, 0.f, 0.f, 0.f);
    float4 hb[2] = {z4, z4}, ob[2] = {z4, z4}, tb[2] = {z4, z4};
    #pragma unroll
    for (int j = 0; j < 2; ++j) {
        const int y = Y0 - WARM + j;
        if (cok && (unsigned)y < (unsigned)IMG_H) {
            hb[j] = *reinterpret_cast<const float4*>(hand + base + (size_t)y * IMG_W + c0);
            ob[j] = *reinterpret_cast<const float4*>(obj  + base + (size_t)y * IMG_W + c0);
        }
    }

    // 5-stage pipeline: (prev, cur) rows per stage per column, zero-init
    u64 pA[WARM], cA[WARM], pB[WARM], cB[WARM];
    u64 pC[WARM], cC[WARM], pD[WARM], cD[WARM];
    #pragma unroll
    for (int k = 0; k < WARM; ++k) {
        pA[k] = cA[k] = pB[k] = cB[k] = 0ULL;
        pC[k] = cC[k] = pD[k] = cD[k] = 0ULL;
    }

    float acc = 0.0f;
    int yi = Y0 - WARM;

    #pragma unroll 2
    for (int i = 0; i < RITER; ++i) {
        const int slot = i & 1;

        // ---- consume prefetched rows for this iteration ----
        const float4 h4 = hb[slot];
        const float4 o4 = ob[slot];
        const float4 t4 = tb[slot];

        // ---- issue prefetch for iteration i+2 immediately ----
        {
            const int yp = yi + 2;
            float4 hn = z4, on = z4;
            if ((i + 2 < RITER) && cok && (unsigned)yp < (unsigned)IMG_H) {
                hn = *reinterpret_cast<const float4*>(hp);
                on = *reinterpret_cast<const float4*>(op);
            }
            hb[slot] = hn;
            ob[slot] = on;
            if ((i + 2 >= 2 * WARM) && (i + 2 < RITER) && anyv)
                tb[slot] = *reinterpret_cast<const float4*>(tp);
        }

        u64 nA = f2pack(h4.x, o4.x);
        u64 nB = f2pack(h4.y, o4.y);
        u64 nC = f2pack(h4.z, o4.z);
        u64 nD = f2pack(h4.w, o4.w);

        // ---- 5-stage cascade: stage k emits one row of iteration k+1 ----
        #pragma unroll
        for (int k = 0; k < WARM; ++k) {
            const u64 lA = __shfl_up_sync(0xffffffffu,  cD[k], 1);  // colA left
            const u64 rD = __shfl_down_sync(0xffffffffu, cA[k], 1); // colD right
            u64 oA = f2add(f2add(pA[k], cA[k]), f2add(lA,    cB[k]));
            u64 oB = f2add(f2add(pB[k], cB[k]), f2add(cA[k], cC[k]));
            u64 oC = f2add(f2add(pC[k], cC[k]), f2add(cB[k], cD[k]));
            u64 oD = f2add(f2add(pD[k], cD[k]), f2add(cC[k], rD));
            oA = f2add(oA, nA);
            oB = f2add(oB, nB);
            oC = f2add(oC, nC);
            oD = f2add(oD, nD);
            pA[k] = cA[k]; cA[k] = nA;
            pB[k] = cB[k]; cB[k] = nB;
            pC[k] = cC[k]; cC[k] = nC;
            pD[k] = cD[k]; cD[k] = nD;
            nA = oA; nB = oB; nC = oC; nD = oD;
        }

        // ---- BCE on stage-5 output row (valid once i >= 10) ----
        if (i >= 2 * WARM) {                    // warp-uniform condition
            float h0, q0, h1, q1, h2, q2, h3, q3;
            f2unpack(nA, h0, q0);
            f2unpack(nB, h1, q1);
            f2unpack(nC, h2, q2);
            f2unpack(nD, h3, q3);
            const float p0 = fminf(h0, 1.f) * fminf(q0, 1.f);
            const float p1 = fminf(h1, 1.f) * fminf(q1, 1.f);
            const float p2 = fminf(h2, 1.f) * fminf(q2, 1.f);
            const float p3 = fminf(h3, 1.f) * fminf(q3, 1.f);

            // fast path: p == 1 -> lp = 0, l1p = -100 exactly (>99% of pixels)
            const bool fast = (!v0 | (p0 == 1.f)) & (!v1 | (p1 == 1.f))
                            & (!v2 | (p2 == 1.f)) & (!v3 | (p3 == 1.f));
            if (__all_sync(0xffffffffu, fast)) {
                float s = 0.f;
                if (v0) s += 1.f - t4.x;
                if (v1) s += 1.f - t4.y;
                if (v2) s += 1.f - t4.z;
                if (v3) s += 1.f - t4.w;
                acc -= 100.f * s;
            } else {
                {
                    const float lp  = fmaxf(__logf(p0),       -100.f);
                    const float l1p = fmaxf(__logf(1.f - p0), -100.f);
                    if (v0) acc += l1p + t4.x * (lp - l1p);
                }
                {
                    const float lp  = fmaxf(__logf(p1),       -100.f);
                    const float l1p = fmaxf(__logf(1.f - p1), -100.f);
                    if (v1) acc += l1p + t4.y * (lp - l1p);
                }
                {
                    const float lp  = fmaxf(__logf(p2),       -100.f);
                    const float l1p = fmaxf(__logf(1.f - p2), -100.f);
                    if (v2) acc += l1p + t4.z * (lp - l1p);
                }
                {
                    const float lp  = fmaxf(__logf(p3),       -100.f);
                    const float l1p = fmaxf(__logf(1.f - p3), -100.f);
                    if (v3) acc += l1p + t4.w * (lp - l1p);
                }
            }
        }

        hp += IMG_W; op += IMG_W; tp += IMG_W;
        ++yi;
    }

    // ---- warp then block reduction, one atomic per block ----
    #pragma unroll
    for (int off = 16; off > 0; off >>= 1)
        acc += __shfl_down_sync(0xffffffffu, acc, off);
    if (lane == 0) wsum[warp] = acc;
    __syncthreads();
    if (tid == 0) {
        float s = 0.0f;
        #pragma unroll
        for (int w = 0; w < WPB; ++w) s += wsum[w];
        const float scale = -1.0f / ((float)IMG_N * IMG_H * IMG_W);
        atomicAdd(out, s * scale);
    }
}

extern "C" void kernel_launch(void* const* d_in, const int* in_sizes, int n_in,
                              void* d_out, int out_size)
{
    const float* hand = (const float*)d_in[0];
    const float* obj  = (const float*)d_in[1];
    const float* targ = (const float*)d_in[2];
    float* out = (float*)d_out;

    bbl_init_out<<<1, 1>>>(out);
    bbl_s4p_kernel<<<NBLOCKS, NTHREADS>>>(hand, obj, targ, out);
}